// round 1
// baseline (speedup 1.0000x reference)
#include <cuda_runtime.h>
#include <math.h>

#define NN     128
#define PLANE  (NN*NN)        // 16384
#define STRIDE 129            // padded row stride (float2) to tame bank conflicts
#define BATCH  64
#define NJ     4
#define NL     4
#define NPAIR  6
#define TFFT   512

// ---------------- device scratch (no allocations allowed) ----------------
static __device__ float2 g_ihat [BATCH * PLANE];                 // 8 MB,  bitrev order
static __device__ float2 g_u1hat[BATCH * NJ * NL * PLANE];       // 134 MB, bitrev order
static __device__ float  g_psi  [NJ * NL * PLANE];               // 1 MB,  bitrev order
static __device__ float  g_s0   [BATCH];
static __device__ float  g_s1p  [BATCH * NJ * NL];               // per-(b,j,l) partials
static __device__ float  g_s2p  [BATCH * NPAIR * NL * NL];       // per-(b,pair,l1,l2)

__device__ __constant__ int PJ1[NPAIR] = {0,0,0,1,1,2};
__device__ __constant__ int PJ2[NPAIR] = {1,2,3,2,3,3};

// ---------------- helpers ----------------
__device__ __forceinline__ float2 cmul(float2 a, float2 b) {
    return make_float2(a.x*b.x - a.y*b.y, a.x*b.y + a.y*b.x);
}

__device__ __forceinline__ void init_tw(float2* tw, int tid) {
    if (tid < 64) {
        float ang = -6.283185307179586f * (float)tid * (1.0f/128.0f);
        float s, c;
        __sincosf(ang, &s, &c);
        tw[tid] = make_float2(c, s);   // W_128^k = exp(-2*pi*i*k/128)
    }
}

// Forward 2D FFT, DIF radix-2, natural in -> 2D-bit-reversed out. In shared.
// Caller must __syncthreads() after filling S.
__device__ void fft2_fwd(float2* S, const float2* tw, int tid) {
    // row transforms (contiguous dim). lanes spread over rows -> 2-way conflicts max
    #pragma unroll
    for (int s = 0; s < 7; ++s) {
        int m = 64 >> s;
        for (int q = tid; q < 8192; q += TFFT) {
            int row = q & 127;
            int t   = q >> 7;            // butterfly index within row, 0..63
            int j   = t & (m - 1);
            int g   = t >> (6 - s);
            int p1  = row * STRIDE + g * (m << 1) + j;
            int p2  = p1 + m;
            float2 u = S[p1], v = S[p2];
            float2 w = tw[j << s];
            S[p1] = make_float2(u.x + v.x, u.y + v.y);
            float2 d = make_float2(u.x - v.x, u.y - v.y);
            S[p2] = cmul(d, w);
        }
        __syncthreads();
    }
    // column transforms. lanes spread over columns -> conflict-free
    #pragma unroll
    for (int s = 0; s < 7; ++s) {
        int m = 64 >> s;
        for (int q = tid; q < 8192; q += TFFT) {
            int col = q & 127;
            int t   = q >> 7;
            int j   = t & (m - 1);
            int g   = t >> (6 - s);
            int p1  = (g * (m << 1) + j) * STRIDE + col;
            int p2  = p1 + m * STRIDE;
            float2 u = S[p1], v = S[p2];
            float2 w = tw[j << s];
            S[p1] = make_float2(u.x + v.x, u.y + v.y);
            float2 d = make_float2(u.x - v.x, u.y - v.y);
            S[p2] = cmul(d, w);
        }
        __syncthreads();
    }
}

// Inverse 2D FFT (unnormalized), DIT radix-2, 2D-bit-reversed in -> natural out.
__device__ void fft2_inv(float2* S, const float2* tw, int tid) {
    #pragma unroll
    for (int s = 6; s >= 0; --s) {    // rows
        int m = 64 >> s;
        for (int q = tid; q < 8192; q += TFFT) {
            int row = q & 127;
            int t   = q >> 7;
            int j   = t & (m - 1);
            int g   = t >> (6 - s);
            int p1  = row * STRIDE + g * (m << 1) + j;
            int p2  = p1 + m;
            float2 w = tw[j << s]; w.y = -w.y;       // conj -> W^{+}
            float2 u = S[p1];
            float2 v = cmul(S[p2], w);
            S[p1] = make_float2(u.x + v.x, u.y + v.y);
            S[p2] = make_float2(u.x - v.x, u.y - v.y);
        }
        __syncthreads();
    }
    #pragma unroll
    for (int s = 6; s >= 0; --s) {    // cols
        int m = 64 >> s;
        for (int q = tid; q < 8192; q += TFFT) {
            int col = q & 127;
            int t   = q >> 7;
            int j   = t & (m - 1);
            int g   = t >> (6 - s);
            int p1  = (g * (m << 1) + j) * STRIDE + col;
            int p2  = p1 + m * STRIDE;
            float2 w = tw[j << s]; w.y = -w.y;
            float2 u = S[p1];
            float2 v = cmul(S[p2], w);
            S[p1] = make_float2(u.x + v.x, u.y + v.y);
            S[p2] = make_float2(u.x - v.x, u.y - v.y);
        }
        __syncthreads();
    }
}

// Deterministic block reduction; result valid on tid==0 only.
__device__ float block_sum(float v, float* red, int tid) {
    #pragma unroll
    for (int o = 16; o > 0; o >>= 1) v += __shfl_down_sync(0xffffffffu, v, o);
    if ((tid & 31) == 0) red[tid >> 5] = v;
    __syncthreads();
    float total = 0.0f;
    if (tid == 0) {
        #pragma unroll
        for (int w = 0; w < TFFT / 32; ++w) total += red[w];
    }
    return total;
}

// ---------------- kernel 1: generate Morlet bank, pre-permuted to bitrev ----------------
__global__ void k_psi() {
    int idx = blockIdx.x * blockDim.x + threadIdx.x;
    if (idx >= NJ * NL * PLANE) return;
    int p   = idx >> 14;            // plane = j*4 + l
    int pos = idx & (PLANE - 1);
    int R = pos >> 7, C = pos & 127;
    int r = __brev((unsigned)R) >> 25;   // 7-bit reversal
    int c = __brev((unsigned)C) >> 25;
    int j = p >> 2, l = p & 3;
    float fr = (float)(r < 64 ? r : r - 128) * (6.283185307179586f / 128.0f); // kx (rows)
    float fc = (float)(c < 64 ? c : c - 128) * (6.283185307179586f / 128.0f); // ky (cols)
    float k0    = 2.356194490192345f / (float)(1 << j);  // 3*pi/4 / 2^j
    float sigma = 0.8f * (float)(1 << j);
    float s2    = sigma * sigma;
    float theta = 0.7853981633974483f * (float)l;        // pi*l/4
    float k0x = k0 * cosf(theta), k0y = k0 * sinf(theta);
    float beta = expf(-0.5f * s2 * k0 * k0);
    float dx = fr - k0x, dy = fc - k0y;
    float g1 = expf(-0.5f * s2 * (dx*dx + dy*dy));
    float g0 = expf(-0.5f * s2 * (fr*fr + fc*fc));
    g_psi[idx] = g1 - beta * g0;
}

// ---------------- kernel 2: fft2 of images + s0 ----------------
__global__ void __launch_bounds__(TFFT, 1) k_img(const float* __restrict__ img) {
    extern __shared__ unsigned char smraw[];
    float2* S   = (float2*)smraw;
    float2* tw  = S + NN * STRIDE;
    float*  red = (float*)(tw + 64);
    int b = blockIdx.x, tid = threadIdx.x;
    init_tw(tw, tid);
    const float* ip = img + (size_t)b * PLANE;
    float lsum = 0.0f;
    for (int i = tid; i < PLANE; i += TFFT) {
        float v = ip[i];
        lsum += v;
        S[(i >> 7) * STRIDE + (i & 127)] = make_float2(v, 0.0f);
    }
    __syncthreads();
    float tot = block_sum(lsum, red, tid);
    if (tid == 0) g_s0[b] = tot * (1.0f / 16384.0f);
    __syncthreads();
    fft2_fwd(S, tw, tid);
    float2* op = g_ihat + (size_t)b * PLANE;
    for (int i = tid; i < PLANE; i += TFFT)
        op[i] = S[(i >> 7) * STRIDE + (i & 127)];
}

// ---------------- kernel 3: order 1 (ifft -> |.| -> s1 partial -> fft -> u1_hat) ----------------
__global__ void __launch_bounds__(TFFT, 1) k_o1() {
    extern __shared__ unsigned char smraw[];
    float2* S   = (float2*)smraw;
    float2* tw  = S + NN * STRIDE;
    float*  red = (float*)(tw + 64);
    int tid = threadIdx.x;
    int b  = blockIdx.x >> 4;
    int j1 = (blockIdx.x >> 2) & 3;
    int l1 = blockIdx.x & 3;
    init_tw(tw, tid);
    const float2* ih = g_ihat + (size_t)b * PLANE;
    const float*  ps = g_psi + (size_t)(j1 * NL + l1) * PLANE;
    for (int i = tid; i < PLANE; i += TFFT) {
        float2 v = ih[i];
        float  p = ps[i];
        S[(i >> 7) * STRIDE + (i & 127)] = make_float2(v.x * p, v.y * p);
    }
    __syncthreads();
    fft2_inv(S, tw, tid);
    float lsum = 0.0f;
    for (int i = tid; i < PLANE; i += TFFT) {
        int pos = (i >> 7) * STRIDE + (i & 127);
        float2 z = S[pos];
        float mag = sqrtf(z.x * z.x + z.y * z.y) * (1.0f / 16384.0f);  // u1, normalized ifft
        S[pos] = make_float2(mag, 0.0f);
        lsum += mag;
    }
    __syncthreads();
    float tot = block_sum(lsum, red, tid);
    if (tid == 0) g_s1p[blockIdx.x] = tot;
    __syncthreads();
    fft2_fwd(S, tw, tid);
    float2* op = g_u1hat + (size_t)blockIdx.x * PLANE;
    for (int i = tid; i < PLANE; i += TFFT)
        op[i] = S[(i >> 7) * STRIDE + (i & 127)];
}

// ---------------- kernel 4: order 2 (mul -> ifft -> sum |.|) ----------------
__global__ void __launch_bounds__(TFFT, 1) k_o2() {
    extern __shared__ unsigned char smraw[];
    float2* S   = (float2*)smraw;
    float2* tw  = S + NN * STRIDE;
    float*  red = (float*)(tw + 64);
    int tid = threadIdx.x;
    int b    = blockIdx.x / 96;
    int rem  = blockIdx.x - b * 96;
    int pair = rem >> 4;
    int l1   = (rem >> 2) & 3;
    int l2   = rem & 3;
    int j1 = PJ1[pair], j2 = PJ2[pair];
    init_tw(tw, tid);
    const float2* uh = g_u1hat + (size_t)(((b * NJ + j1) * NL) + l1) * PLANE;
    const float*  ps = g_psi + (size_t)(j2 * NL + l2) * PLANE;
    for (int i = tid; i < PLANE; i += TFFT) {
        float2 v = uh[i];
        float  p = ps[i];
        S[(i >> 7) * STRIDE + (i & 127)] = make_float2(v.x * p, v.y * p);
    }
    __syncthreads();
    fft2_inv(S, tw, tid);
    float lsum = 0.0f;
    for (int i = tid; i < PLANE; i += TFFT) {
        float2 z = S[(i >> 7) * STRIDE + (i & 127)];
        lsum += sqrtf(z.x * z.x + z.y * z.y);   // unnormalized; scaled in k_head
    }
    __syncthreads();
    float tot = block_sum(lsum, red, tid);
    if (tid == 0) g_s2p[blockIdx.x] = tot;
}

// ---------------- kernel 5: deterministic combine + MLP head ----------------
__global__ void k_head(const float* __restrict__ fc1w, const float* __restrict__ fc1b,
                       const float* __restrict__ fc2w, const float* __restrict__ fc2b,
                       float* __restrict__ out) {
    int b = blockIdx.x;
    if (threadIdx.x != 0) return;
    float coeff[11];
    coeff[0] = g_s0[b];
    #pragma unroll
    for (int j = 0; j < 4; ++j) {
        float s = 0.0f;
        #pragma unroll
        for (int l = 0; l < 4; ++l) s += g_s1p[(b * 4 + j) * 4 + l];
        coeff[1 + j] = s * (1.0f / (4.0f * 16384.0f));
    }
    #pragma unroll
    for (int p = 0; p < 6; ++p) {
        float s = 0.0f;
        #pragma unroll
        for (int k = 0; k < 16; ++k) s += g_s2p[(b * 6 + p) * 16 + k];
        // ifft normalization (1/16384) * mean over (l1,l2,N,N)
        coeff[5 + p] = s * (1.0f / 16384.0f) * (1.0f / (16.0f * 16384.0f));
    }
    float h[4];
    #pragma unroll
    for (int k = 0; k < 4; ++k) {
        float a = fc1b[k];
        #pragma unroll
        for (int i = 0; i < 11; ++i) a += coeff[i] * fc1w[k * 11 + i];
        h[k] = fmaxf(a, 0.0f);
    }
    #pragma unroll
    for (int o = 0; o < 10; ++o) {
        float a = fc2b[o];
        #pragma unroll
        for (int k = 0; k < 4; ++k) a += h[k] * fc2w[o * 4 + k];
        out[b * 10 + o] = 1.0f / (1.0f + expf(-a));
    }
}

// ---------------- launch ----------------
extern "C" void kernel_launch(void* const* d_in, const int* in_sizes, int n_in,
                              void* d_out, int out_size) {
    (void)in_sizes; (void)n_in; (void)out_size;
    const float* img  = (const float*)d_in[0];
    const float* fc1w = (const float*)d_in[1];
    const float* fc1b = (const float*)d_in[2];
    const float* fc2w = (const float*)d_in[3];
    const float* fc2b = (const float*)d_in[4];
    float* out = (float*)d_out;

    const size_t SMEM_SZ = (size_t)(NN * STRIDE + 64) * sizeof(float2) + (TFFT / 32) * sizeof(float);
    cudaFuncSetAttribute(k_img, cudaFuncAttributeMaxDynamicSharedMemorySize, (int)SMEM_SZ);
    cudaFuncSetAttribute(k_o1,  cudaFuncAttributeMaxDynamicSharedMemorySize, (int)SMEM_SZ);
    cudaFuncSetAttribute(k_o2,  cudaFuncAttributeMaxDynamicSharedMemorySize, (int)SMEM_SZ);

    k_psi<<<(NJ * NL * PLANE + 255) / 256, 256>>>();
    k_img<<<BATCH, TFFT, SMEM_SZ>>>(img);
    k_o1 <<<BATCH * NJ * NL, TFFT, SMEM_SZ>>>();
    k_o2 <<<BATCH * NPAIR * NL * NL, TFFT, SMEM_SZ>>>();
    k_head<<<BATCH, 32>>>(fc1w, fc1b, fc2w, fc2b, out);
}

// round 2
// speedup vs baseline: 1.8795x; 1.8795x over previous
#include <cuda_runtime.h>
#include <math.h>

#define NN     128
#define PLANE  16384
#define STRIDE 129            // padded row stride (float2)
#define BATCH  64
#define NJ     4
#define NL     4
#define NPAIR  6
#define NT     1024           // threads per FFT block (32 warps)

// ---------------- device scratch ----------------
static __device__ float2 g_ihat [BATCH * PLANE];                 // bitrev order
static __device__ float2 g_u1hat[BATCH * NJ * NL * PLANE];       // bitrev order
static __device__ float  g_psi  [NJ * NL * PLANE];               // bitrev order
static __device__ float  g_s0   [BATCH];
static __device__ float  g_s1p  [BATCH * NJ * NL];
static __device__ float  g_s2p  [BATCH * NPAIR * NL * NL];

__device__ __constant__ int PJ1[NPAIR] = {0,0,0,1,1,2};
__device__ __constant__ int PJ2[NPAIR] = {1,2,3,2,3,3};

// ---------------- complex helpers ----------------
__device__ __forceinline__ float2 cmulf(float2 a, float2 b) {
    return make_float2(a.x*b.x - a.y*b.y, a.x*b.y + a.y*b.x);
}
__device__ __forceinline__ float2 caddf(float2 a, float2 b){ return make_float2(a.x+b.x, a.y+b.y); }
__device__ __forceinline__ float2 csubf(float2 a, float2 b){ return make_float2(a.x-b.x, a.y-b.y); }

__device__ __forceinline__ void init_tw(float2* tw, int tid) {
    if (tid < 64) {
        float s, c;
        __sincosf(-6.283185307179586f * (float)tid * (1.0f/128.0f), &s, &c);
        tw[tid] = make_float2(c, s);   // W_128^k
    }
}

__device__ __forceinline__ float2 shflx(float2 v, int h) {
    float2 o;
    o.x = __shfl_xor_sync(0xffffffffu, v.x, h);
    o.y = __shfl_xor_sync(0xffffffffu, v.y, h);
    return o;
}

// ---------------- 128-pt FFT: 16 lanes x 8 regs, position p = u + 16*i ----------------
// Forward DIF: natural positions in -> bit-reversed positions out (in-place).
__device__ __forceinline__ void fft128_fwd(float2 x[8], int u, const float2* __restrict__ tw) {
    // s=0, m=64: pairs (i, i+4), j = u+16*i
    #pragma unroll
    for (int i = 0; i < 4; ++i) {
        float2 a = x[i], b = x[i+4];
        x[i]   = caddf(a, b);
        x[i+4] = cmulf(csubf(a, b), tw[u + 16*i]);
    }
    // s=1, m=32: pairs (k+i, k+i+2), j = u+16*i (i<2)
    #pragma unroll
    for (int k = 0; k < 8; k += 4)
        #pragma unroll
        for (int i = 0; i < 2; ++i) {
            float2 a = x[k+i], b = x[k+i+2];
            x[k+i]   = caddf(a, b);
            x[k+i+2] = cmulf(csubf(a, b), tw[(u + 16*i) << 1]);
        }
    // s=2, m=16: pairs (i, i+1), j = u
    {
        float2 w = tw[u << 2];
        #pragma unroll
        for (int i = 0; i < 8; i += 2) {
            float2 a = x[i], b = x[i+1];
            x[i]   = caddf(a, b);
            x[i+1] = cmulf(csubf(a, b), w);
        }
    }
    // s=3..6: shuffle stages, h = 8,4,2,1
    #pragma unroll
    for (int s = 3; s < 7; ++s) {
        int h = 64 >> s;
        bool lower = (u & h) == 0;
        float2 w = tw[(u & (h - 1)) << s];
        #pragma unroll
        for (int i = 0; i < 8; ++i) {
            float2 v = x[i];
            float2 o = shflx(v, h);
            x[i] = lower ? caddf(v, o) : cmulf(csubf(o, v), w);
        }
    }
}

// Inverse DIT (unnormalized): bit-reversed positions in -> natural out (in-place).
__device__ __forceinline__ void fft128_inv(float2 x[8], int u, const float2* __restrict__ tw) {
    // s=6..3: shuffle stages, h = 1,2,4,8
    #pragma unroll
    for (int s = 6; s >= 3; --s) {
        int h = 64 >> s;
        bool lower = (u & h) == 0;
        float2 w = tw[(u & (h - 1)) << s]; w.y = -w.y;
        #pragma unroll
        for (int i = 0; i < 8; ++i) {
            float2 t = lower ? x[i] : cmulf(x[i], w);
            float2 o = shflx(t, h);
            x[i] = lower ? caddf(t, o) : csubf(o, t);
        }
    }
    // s=2, m=16
    {
        float2 w = tw[u << 2]; w.y = -w.y;
        #pragma unroll
        for (int i = 0; i < 8; i += 2) {
            float2 a = x[i], v = cmulf(x[i+1], w);
            x[i]   = caddf(a, v);
            x[i+1] = csubf(a, v);
        }
    }
    // s=1, m=32
    #pragma unroll
    for (int k = 0; k < 8; k += 4)
        #pragma unroll
        for (int i = 0; i < 2; ++i) {
            float2 w = tw[(u + 16*i) << 1]; w.y = -w.y;
            float2 a = x[k+i], v = cmulf(x[k+i+2], w);
            x[k+i]   = caddf(a, v);
            x[k+i+2] = csubf(a, v);
        }
    // s=0, m=64
    #pragma unroll
    for (int i = 0; i < 4; ++i) {
        float2 w = tw[u + 16*i]; w.y = -w.y;
        float2 a = x[i], v = cmulf(x[i+4], w);
        x[i]   = caddf(a, v);
        x[i+4] = csubf(a, v);
    }
}

// Deterministic block reduction; valid on tid==0. Contains one __syncthreads
// (which also orders all prior shared stores before subsequent shared loads).
__device__ __forceinline__ float block_sum(float v, float* red, int tid) {
    #pragma unroll
    for (int o = 16; o > 0; o >>= 1) v += __shfl_down_sync(0xffffffffu, v, o);
    if ((tid & 31) == 0) red[tid >> 5] = v;
    __syncthreads();
    float total = 0.0f;
    if (tid == 0) {
        #pragma unroll
        for (int w = 0; w < NT / 32; ++w) total += red[w];
    }
    return total;
}

// ---------------- kernel 1: Morlet bank, pre-permuted to 2D-bitrev ----------------
__global__ void k_psi() {
    int idx = blockIdx.x * blockDim.x + threadIdx.x;
    if (idx >= NJ * NL * PLANE) return;
    int p   = idx >> 14;
    int pos = idx & (PLANE - 1);
    int R = pos >> 7, C = pos & 127;
    int r = __brev((unsigned)R) >> 25;
    int c = __brev((unsigned)C) >> 25;
    int j = p >> 2, l = p & 3;
    float fr = (float)(r < 64 ? r : r - 128) * (6.283185307179586f / 128.0f);
    float fc = (float)(c < 64 ? c : c - 128) * (6.283185307179586f / 128.0f);
    float k0    = 2.356194490192345f / (float)(1 << j);
    float sigma = 0.8f * (float)(1 << j);
    float s2    = sigma * sigma;
    float theta = 0.7853981633974483f * (float)l;
    float k0x = k0 * cosf(theta), k0y = k0 * sinf(theta);
    float beta = expf(-0.5f * s2 * k0 * k0);
    float dx = fr - k0x, dy = fc - k0y;
    float g1 = expf(-0.5f * s2 * (dx*dx + dy*dy));
    float g0 = expf(-0.5f * s2 * (fr*fr + fc*fc));
    g_psi[idx] = g1 - beta * g0;
}

// ---------------- kernel 2: fft2(image) + s0 ----------------
__global__ void __launch_bounds__(NT, 1) k_img(const float* __restrict__ img) {
    extern __shared__ unsigned char smraw[];
    float2* S   = (float2*)smraw;
    float2* tw  = S + NN * STRIDE;
    float*  red = (float*)(tw + 64);
    int b = blockIdx.x, tid = threadIdx.x;
    int u = tid & 15, g = tid >> 4;
    init_tw(tw, tid);
    __syncthreads();
    const float* ip = img + (size_t)b * PLANE;
    float lsum = 0.0f;
    #pragma unroll
    for (int iter = 0; iter < 2; ++iter) {          // row pass (forward)
        int r = g + 64 * iter;
        float2 x[8];
        #pragma unroll
        for (int i = 0; i < 8; ++i) {
            float v = ip[r * NN + u + 16*i];
            lsum += v;
            x[i] = make_float2(v, 0.0f);
        }
        fft128_fwd(x, u, tw);
        #pragma unroll
        for (int i = 0; i < 8; ++i) S[r * STRIDE + u + 16*i] = x[i];
    }
    float tot = block_sum(lsum, red, tid);          // sync inside orders S stores
    if (tid == 0) g_s0[b] = tot * (1.0f / 16384.0f);
    #pragma unroll
    for (int iter = 0; iter < 2; ++iter) {          // column pass (forward)
        int c = g + 64 * iter;
        float2 x[8];
        #pragma unroll
        for (int i = 0; i < 8; ++i) x[i] = S[(u + 16*i) * STRIDE + c];
        fft128_fwd(x, u, tw);
        #pragma unroll
        for (int i = 0; i < 8; ++i) S[(u + 16*i) * STRIDE + c] = x[i];
    }
    __syncthreads();
    float2* op = g_ihat + (size_t)b * PLANE;
    for (int i = tid; i < PLANE; i += NT)
        op[i] = S[(i >> 7) * STRIDE + (i & 127)];
}

// ---------------- kernel 3: order 1 ----------------
__global__ void __launch_bounds__(NT, 1) k_o1() {
    extern __shared__ unsigned char smraw[];
    float2* S   = (float2*)smraw;
    float2* tw  = S + NN * STRIDE;
    float*  red = (float*)(tw + 64);
    int tid = threadIdx.x;
    int u = tid & 15, g = tid >> 4;
    int b  = blockIdx.x >> 4;
    int j1 = (blockIdx.x >> 2) & 3;
    int l1 = blockIdx.x & 3;
    init_tw(tw, tid);
    __syncthreads();
    const float2* ih = g_ihat + (size_t)b * PLANE;
    const float*  ps = g_psi + (size_t)(j1 * NL + l1) * PLANE;
    #pragma unroll
    for (int iter = 0; iter < 2; ++iter) {          // inverse rows (bitrev in)
        int r = g + 64 * iter;
        float2 x[8];
        #pragma unroll
        for (int i = 0; i < 8; ++i) {
            int p = r * NN + u + 16*i;
            float2 v = ih[p];
            float  f = ps[p];
            x[i] = make_float2(v.x * f, v.y * f);
        }
        fft128_inv(x, u, tw);
        #pragma unroll
        for (int i = 0; i < 8; ++i) S[r * STRIDE + u + 16*i] = x[i];
    }
    __syncthreads();
    float lsum = 0.0f;
    #pragma unroll
    for (int iter = 0; iter < 2; ++iter) {          // inverse cols -> |.| -> forward cols
        int c = g + 64 * iter;
        float2 x[8];
        #pragma unroll
        for (int i = 0; i < 8; ++i) x[i] = S[(u + 16*i) * STRIDE + c];
        fft128_inv(x, u, tw);
        #pragma unroll
        for (int i = 0; i < 8; ++i) {
            float m = sqrtf(x[i].x * x[i].x + x[i].y * x[i].y) * (1.0f / 16384.0f);
            lsum += m;
            x[i] = make_float2(m, 0.0f);
        }
        fft128_fwd(x, u, tw);
        #pragma unroll
        for (int i = 0; i < 8; ++i) S[(u + 16*i) * STRIDE + c] = x[i];
    }
    float tot = block_sum(lsum, red, tid);          // sync inside orders S stores
    if (tid == 0) g_s1p[blockIdx.x] = tot;
    float2* op = g_u1hat + (size_t)blockIdx.x * PLANE;
    #pragma unroll
    for (int iter = 0; iter < 2; ++iter) {          // forward rows, write out from regs
        int r = g + 64 * iter;
        float2 x[8];
        #pragma unroll
        for (int i = 0; i < 8; ++i) x[i] = S[r * STRIDE + u + 16*i];
        fft128_fwd(x, u, tw);
        #pragma unroll
        for (int i = 0; i < 8; ++i) op[r * NN + u + 16*i] = x[i];
    }
}

// ---------------- kernel 4: order 2 ----------------
__global__ void __launch_bounds__(NT, 1) k_o2() {
    extern __shared__ unsigned char smraw[];
    float2* S   = (float2*)smraw;
    float2* tw  = S + NN * STRIDE;
    float*  red = (float*)(tw + 64);
    int tid = threadIdx.x;
    int u = tid & 15, g = tid >> 4;
    int b    = blockIdx.x / 96;
    int rem  = blockIdx.x - b * 96;
    int pair = rem >> 4;
    int l1   = (rem >> 2) & 3;
    int l2   = rem & 3;
    int j1 = PJ1[pair], j2 = PJ2[pair];
    init_tw(tw, tid);
    __syncthreads();
    const float2* uh = g_u1hat + (size_t)(((b * NJ + j1) * NL) + l1) * PLANE;
    const float*  ps = g_psi + (size_t)(j2 * NL + l2) * PLANE;
    #pragma unroll
    for (int iter = 0; iter < 2; ++iter) {          // inverse rows
        int r = g + 64 * iter;
        float2 x[8];
        #pragma unroll
        for (int i = 0; i < 8; ++i) {
            int p = r * NN + u + 16*i;
            float2 v = uh[p];
            float  f = ps[p];
            x[i] = make_float2(v.x * f, v.y * f);
        }
        fft128_inv(x, u, tw);
        #pragma unroll
        for (int i = 0; i < 8; ++i) S[r * STRIDE + u + 16*i] = x[i];
    }
    __syncthreads();
    float lsum = 0.0f;
    #pragma unroll
    for (int iter = 0; iter < 2; ++iter) {          // inverse cols, |.| summed from regs
        int c = g + 64 * iter;
        float2 x[8];
        #pragma unroll
        for (int i = 0; i < 8; ++i) x[i] = S[(u + 16*i) * STRIDE + c];
        fft128_inv(x, u, tw);
        #pragma unroll
        for (int i = 0; i < 8; ++i)
            lsum += sqrtf(x[i].x * x[i].x + x[i].y * x[i].y);
    }
    float tot = block_sum(lsum, red, tid);
    if (tid == 0) g_s2p[blockIdx.x] = tot;
}

// ---------------- kernel 5: combine + MLP ----------------
__global__ void k_head(const float* __restrict__ fc1w, const float* __restrict__ fc1b,
                       const float* __restrict__ fc2w, const float* __restrict__ fc2b,
                       float* __restrict__ out) {
    int b = blockIdx.x;
    if (threadIdx.x != 0) return;
    float coeff[11];
    coeff[0] = g_s0[b];
    #pragma unroll
    for (int j = 0; j < 4; ++j) {
        float s = 0.0f;
        #pragma unroll
        for (int l = 0; l < 4; ++l) s += g_s1p[(b * 4 + j) * 4 + l];
        coeff[1 + j] = s * (1.0f / (4.0f * 16384.0f));
    }
    #pragma unroll
    for (int p = 0; p < 6; ++p) {
        float s = 0.0f;
        #pragma unroll
        for (int k = 0; k < 16; ++k) s += g_s2p[(b * 6 + p) * 16 + k];
        coeff[5 + p] = s * (1.0f / 16384.0f) * (1.0f / (16.0f * 16384.0f));
    }
    float h[4];
    #pragma unroll
    for (int k = 0; k < 4; ++k) {
        float a = fc1b[k];
        #pragma unroll
        for (int i = 0; i < 11; ++i) a += coeff[i] * fc1w[k * 11 + i];
        h[k] = fmaxf(a, 0.0f);
    }
    #pragma unroll
    for (int o = 0; o < 10; ++o) {
        float a = fc2b[o];
        #pragma unroll
        for (int k = 0; k < 4; ++k) a += h[k] * fc2w[o * 4 + k];
        out[b * 10 + o] = 1.0f / (1.0f + expf(-a));
    }
}

// ---------------- launch ----------------
extern "C" void kernel_launch(void* const* d_in, const int* in_sizes, int n_in,
                              void* d_out, int out_size) {
    (void)in_sizes; (void)n_in; (void)out_size;
    const float* img  = (const float*)d_in[0];
    const float* fc1w = (const float*)d_in[1];
    const float* fc1b = (const float*)d_in[2];
    const float* fc2w = (const float*)d_in[3];
    const float* fc2b = (const float*)d_in[4];
    float* out = (float*)d_out;

    const size_t SMEM_SZ = (size_t)(NN * STRIDE + 64) * sizeof(float2) + (NT / 32) * sizeof(float);
    cudaFuncSetAttribute(k_img, cudaFuncAttributeMaxDynamicSharedMemorySize, (int)SMEM_SZ);
    cudaFuncSetAttribute(k_o1,  cudaFuncAttributeMaxDynamicSharedMemorySize, (int)SMEM_SZ);
    cudaFuncSetAttribute(k_o2,  cudaFuncAttributeMaxDynamicSharedMemorySize, (int)SMEM_SZ);

    k_psi<<<(NJ * NL * PLANE + 255) / 256, 256>>>();
    k_img<<<BATCH, NT, SMEM_SZ>>>(img);
    k_o1 <<<BATCH * NJ * NL, NT, SMEM_SZ>>>();
    k_o2 <<<BATCH * NPAIR * NL * NL, NT, SMEM_SZ>>>();
    k_head<<<BATCH, 32>>>(fc1w, fc1b, fc2w, fc2b, out);
}

// round 3
// speedup vs baseline: 2.1996x; 1.1703x over previous
#include <cuda_runtime.h>
#include <math.h>

#define NN     128
#define PLANE  16384
#define STRIDE 129            // padded row stride (float2)
#define BATCH  64
#define NJ     4
#define NL     4
#define NPAIR  6
#define NT     1024           // threads per FFT block (32 warps)

// ---------------- device scratch ----------------
static __device__ float2 g_ihat [BATCH * PLANE];                 // bitrev order
static __device__ float2 g_u1hat[BATCH * NJ * NL * PLANE];       // bitrev order
static __device__ float  g_psi  [NJ * NL * PLANE];               // bitrev order
static __device__ float  g_s0   [BATCH];
static __device__ float  g_s1p  [BATCH * NJ * NL];
static __device__ float  g_s2p  [BATCH * NPAIR * NL * NL];

__device__ __constant__ int PJ1[NPAIR] = {0,0,0,1,1,2};
__device__ __constant__ int PJ2[NPAIR] = {1,2,3,2,3,3};

// ---------------- helpers ----------------
__device__ __forceinline__ float2 cmulf(float2 a, float2 b) {
    return make_float2(a.x*b.x - a.y*b.y, a.x*b.y + a.y*b.x);
}
__device__ __forceinline__ float2 caddf(float2 a, float2 b){ return make_float2(a.x+b.x, a.y+b.y); }
__device__ __forceinline__ float2 csubf(float2 a, float2 b){ return make_float2(a.x-b.x, a.y-b.y); }

__device__ __forceinline__ void init_tw(float2* tw, int tid) {
    if (tid < 128) {
        float s, c;
        __sincosf(-6.283185307179586f * (float)tid * (1.0f/128.0f), &s, &c);
        tw[tid] = make_float2(c, s);   // W_128^k, k=0..127
    }
}

__device__ __forceinline__ float2 shflx(float2 v, int h) {
    float2 o;
    o.x = __shfl_xor_sync(0xffffffffu, v.x, h);
    o.y = __shfl_xor_sync(0xffffffffu, v.y, h);
    return o;
}

__device__ __forceinline__ float fast_mag(float2 z) {
    float m2 = fmaf(z.x, z.x, z.y * z.y);
    float r;
    asm("sqrt.approx.f32 %0, %1;" : "=f"(r) : "f"(m2));
    return r;
}

// ---------------- 128-pt FFT: 16 lanes x 8 regs, position p = u + 16*i ----------------
// Forward DIF: natural in -> bit-reversed out.
__device__ __forceinline__ void fft128_fwd(float2 x[8], int u, const float2* __restrict__ tw) {
    // merged radix-4 (stages m=64,32) on quartets (qi, qi+2, qi+4, qi+6)
    #pragma unroll
    for (int qi = 0; qi < 2; ++qi) {
        float2 a = x[qi], b = x[qi+2], c = x[qi+4], d = x[qi+6];
        float2 t3 = caddf(a, c), t1 = csubf(a, c);
        float2 t4 = caddf(b, d), t2 = csubf(b, d);
        int j = u + 16 * qi;
        float2 w1 = tw[j], w2 = tw[2*j], w3 = tw[3*j];
        x[qi]   = caddf(t3, t4);
        x[qi+2] = cmulf(csubf(t3, t4), w2);
        x[qi+4] = cmulf(make_float2(t1.x + t2.y, t1.y - t2.x), w1);  // (t1 - i t2) W^j
        x[qi+6] = cmulf(make_float2(t1.x - t2.y, t1.y + t2.x), w3);  // (t1 + i t2) W^3j
    }
    // stage m=16: pairs (i, i+1), same twiddle all pairs
    {
        float2 w = tw[u << 2];
        #pragma unroll
        for (int i = 0; i < 8; i += 2) {
            float2 a = x[i], b = x[i+1];
            x[i]   = caddf(a, b);
            x[i+1] = cmulf(csubf(a, b), w);
        }
    }
    // shuffle stages h = 8,4,2,1 — select-free
    #pragma unroll
    for (int s = 3; s < 7; ++s) {
        int h = 64 >> s;
        bool lower = (u & h) == 0;
        float sgn = lower ? 1.0f : -1.0f;
        float2 wst = tw[(u & (h - 1)) << s];
        float2 we  = lower ? make_float2(1.0f, 0.0f) : wst;
        #pragma unroll
        for (int i = 0; i < 8; ++i) {
            float2 v = x[i];
            float2 o = shflx(v, h);
            float2 t = make_float2(fmaf(sgn, v.x, o.x), fmaf(sgn, v.y, o.y));
            x[i] = cmulf(t, we);
        }
    }
}

// Inverse DIT (unnormalized, x16384 total): bit-reversed in -> natural out.
__device__ __forceinline__ void fft128_inv(float2 x[8], int u, const float2* __restrict__ tw) {
    // shuffle stages h = 1,2,4,8 — select-free
    #pragma unroll
    for (int s = 6; s >= 3; --s) {
        int h = 64 >> s;
        bool lower = (u & h) == 0;
        float sgn = lower ? 1.0f : -1.0f;
        float2 wst = tw[(u & (h - 1)) << s];
        float2 we  = lower ? make_float2(1.0f, 0.0f) : make_float2(wst.x, -wst.y);
        #pragma unroll
        for (int i = 0; i < 8; ++i) {
            float2 t = cmulf(x[i], we);
            float2 o = shflx(t, h);
            x[i] = make_float2(fmaf(sgn, t.x, o.x), fmaf(sgn, t.y, o.y));
        }
    }
    // stage m=16 inverse
    {
        float2 w = tw[u << 2]; w.y = -w.y;
        #pragma unroll
        for (int i = 0; i < 8; i += 2) {
            float2 a = x[i], v = cmulf(x[i+1], w);
            x[i]   = caddf(a, v);
            x[i+1] = csubf(a, v);
        }
    }
    // merged inverse radix-4 (stages m=32,64): 3 cmuls per quartet
    #pragma unroll
    for (int qi = 0; qi < 2; ++qi) {
        float2 a = x[qi], b = x[qi+2], c = x[qi+4], d = x[qi+6];
        int j = u + 16 * qi;
        float2 w1 = tw[j],   w2 = tw[2*j],   w3 = tw[3*j];
        w1.y = -w1.y; w2.y = -w2.y; w3.y = -w3.y;
        float2 s1 = cmulf(b, w2);
        float2 s2 = cmulf(c, w1);
        float2 s3 = cmulf(d, w3);
        float2 t3 = caddf(a, s1);                                    // 2*t3
        float2 t4 = csubf(a, s1);                                    // 2*t4
        float2 t1 = caddf(s2, s3);                                   // 2*t1
        float2 t2 = make_float2(s3.y - s2.y, s2.x - s3.x);           // 2*t2 = i(s2-s3)
        x[qi]   = caddf(t3, t1);
        x[qi+4] = csubf(t3, t1);
        x[qi+2] = caddf(t4, t2);
        x[qi+6] = csubf(t4, t2);
    }
}

// Deterministic block reduction; valid on tid==0. Contains one __syncthreads.
__device__ __forceinline__ float block_sum(float v, float* red, int tid) {
    #pragma unroll
    for (int o = 16; o > 0; o >>= 1) v += __shfl_down_sync(0xffffffffu, v, o);
    if ((tid & 31) == 0) red[tid >> 5] = v;
    __syncthreads();
    float total = 0.0f;
    if (tid == 0) {
        #pragma unroll
        for (int w = 0; w < NT / 32; ++w) total += red[w];
    }
    return total;
}

// ---------------- kernel 1: Morlet bank, pre-permuted to 2D-bitrev ----------------
__global__ void k_psi() {
    int idx = blockIdx.x * blockDim.x + threadIdx.x;
    if (idx >= NJ * NL * PLANE) return;
    int p   = idx >> 14;
    int pos = idx & (PLANE - 1);
    int R = pos >> 7, C = pos & 127;
    int r = __brev((unsigned)R) >> 25;
    int c = __brev((unsigned)C) >> 25;
    int j = p >> 2, l = p & 3;
    float fr = (float)(r < 64 ? r : r - 128) * (6.283185307179586f / 128.0f);
    float fc = (float)(c < 64 ? c : c - 128) * (6.283185307179586f / 128.0f);
    float k0    = 2.356194490192345f / (float)(1 << j);
    float sigma = 0.8f * (float)(1 << j);
    float s2    = sigma * sigma;
    float theta = 0.7853981633974483f * (float)l;
    float k0x = k0 * cosf(theta), k0y = k0 * sinf(theta);
    float beta = expf(-0.5f * s2 * k0 * k0);
    float dx = fr - k0x, dy = fc - k0y;
    float g1 = expf(-0.5f * s2 * (dx*dx + dy*dy));
    float g0 = expf(-0.5f * s2 * (fr*fr + fc*fc));
    g_psi[idx] = g1 - beta * g0;
}

// ---------------- kernel 2: fft2(image) + s0 ----------------
__global__ void __launch_bounds__(NT, 1) k_img(const float* __restrict__ img) {
    extern __shared__ unsigned char smraw[];
    float2* S   = (float2*)smraw;
    float2* tw  = S + NN * STRIDE;
    float*  red = (float*)(tw + 128);
    int b = blockIdx.x, tid = threadIdx.x;
    int u = tid & 15, g = tid >> 4;
    init_tw(tw, tid);
    __syncthreads();
    const float* ip = img + (size_t)b * PLANE;
    float lsum = 0.0f;
    #pragma unroll
    for (int iter = 0; iter < 2; ++iter) {          // row pass (forward)
        int r = g + 64 * iter;
        float2 x[8];
        #pragma unroll
        for (int i = 0; i < 8; ++i) {
            float v = ip[r * NN + u + 16*i];
            lsum += v;
            x[i] = make_float2(v, 0.0f);
        }
        fft128_fwd(x, u, tw);
        #pragma unroll
        for (int i = 0; i < 8; ++i) S[r * STRIDE + u + 16*i] = x[i];
    }
    float tot = block_sum(lsum, red, tid);          // sync inside orders S stores
    if (tid == 0) g_s0[b] = tot * (1.0f / 16384.0f);
    #pragma unroll
    for (int iter = 0; iter < 2; ++iter) {          // column pass (forward)
        int c = g + 64 * iter;
        float2 x[8];
        #pragma unroll
        for (int i = 0; i < 8; ++i) x[i] = S[(u + 16*i) * STRIDE + c];
        fft128_fwd(x, u, tw);
        #pragma unroll
        for (int i = 0; i < 8; ++i) S[(u + 16*i) * STRIDE + c] = x[i];
    }
    __syncthreads();
    float2* op = g_ihat + (size_t)b * PLANE;
    for (int i = tid; i < PLANE; i += NT)
        op[i] = S[(i >> 7) * STRIDE + (i & 127)];
}

// ---------------- kernel 3: order 1 ----------------
__global__ void __launch_bounds__(NT, 1) k_o1() {
    extern __shared__ unsigned char smraw[];
    float2* S   = (float2*)smraw;
    float2* tw  = S + NN * STRIDE;
    float*  red = (float*)(tw + 128);
    int tid = threadIdx.x;
    int u = tid & 15, g = tid >> 4;
    int b  = blockIdx.x >> 4;
    int j1 = (blockIdx.x >> 2) & 3;
    int l1 = blockIdx.x & 3;
    init_tw(tw, tid);
    __syncthreads();
    const float2* ih = g_ihat + (size_t)b * PLANE;
    const float*  ps = g_psi + (size_t)(j1 * NL + l1) * PLANE;
    #pragma unroll
    for (int iter = 0; iter < 2; ++iter) {          // inverse rows (bitrev in)
        int r = g + 64 * iter;
        float2 x[8];
        #pragma unroll
        for (int i = 0; i < 8; ++i) {
            int p = r * NN + u + 16*i;
            float2 v = ih[p];
            float  f = ps[p];
            x[i] = make_float2(v.x * f, v.y * f);
        }
        fft128_inv(x, u, tw);
        #pragma unroll
        for (int i = 0; i < 8; ++i) S[r * STRIDE + u + 16*i] = x[i];
    }
    __syncthreads();
    float lsum = 0.0f;
    #pragma unroll
    for (int iter = 0; iter < 2; ++iter) {          // inverse cols -> |.| -> forward cols
        int c = g + 64 * iter;
        float2 x[8];
        #pragma unroll
        for (int i = 0; i < 8; ++i) x[i] = S[(u + 16*i) * STRIDE + c];
        fft128_inv(x, u, tw);
        #pragma unroll
        for (int i = 0; i < 8; ++i) {
            float m = fast_mag(x[i]) * (1.0f / 16384.0f);
            lsum += m;
            x[i] = make_float2(m, 0.0f);
        }
        fft128_fwd(x, u, tw);
        #pragma unroll
        for (int i = 0; i < 8; ++i) S[(u + 16*i) * STRIDE + c] = x[i];
    }
    float tot = block_sum(lsum, red, tid);          // sync inside orders S stores
    if (tid == 0) g_s1p[blockIdx.x] = tot;
    float2* op = g_u1hat + (size_t)blockIdx.x * PLANE;
    #pragma unroll
    for (int iter = 0; iter < 2; ++iter) {          // forward rows, write out from regs
        int r = g + 64 * iter;
        float2 x[8];
        #pragma unroll
        for (int i = 0; i < 8; ++i) x[i] = S[r * STRIDE + u + 16*i];
        fft128_fwd(x, u, tw);
        #pragma unroll
        for (int i = 0; i < 8; ++i) op[r * NN + u + 16*i] = x[i];
    }
}

// ---------------- kernel 4: order 2 ----------------
__global__ void __launch_bounds__(NT, 1) k_o2() {
    extern __shared__ unsigned char smraw[];
    float2* S   = (float2*)smraw;
    float2* tw  = S + NN * STRIDE;
    float*  red = (float*)(tw + 128);
    int tid = threadIdx.x;
    int u = tid & 15, g = tid >> 4;
    int b    = blockIdx.x / 96;
    int rem  = blockIdx.x - b * 96;
    int pair = rem >> 4;
    int l1   = (rem >> 2) & 3;
    int l2   = rem & 3;
    int j1 = PJ1[pair], j2 = PJ2[pair];
    init_tw(tw, tid);
    __syncthreads();
    const float2* uh = g_u1hat + (size_t)(((b * NJ + j1) * NL) + l1) * PLANE;
    const float*  ps = g_psi + (size_t)(j2 * NL + l2) * PLANE;
    #pragma unroll
    for (int iter = 0; iter < 2; ++iter) {          // inverse rows
        int r = g + 64 * iter;
        float2 x[8];
        #pragma unroll
        for (int i = 0; i < 8; ++i) {
            int p = r * NN + u + 16*i;
            float2 v = uh[p];
            float  f = ps[p];
            x[i] = make_float2(v.x * f, v.y * f);
        }
        fft128_inv(x, u, tw);
        #pragma unroll
        for (int i = 0; i < 8; ++i) S[r * STRIDE + u + 16*i] = x[i];
    }
    __syncthreads();
    float lsum = 0.0f;
    #pragma unroll
    for (int iter = 0; iter < 2; ++iter) {          // inverse cols, |.| summed from regs
        int c = g + 64 * iter;
        float2 x[8];
        #pragma unroll
        for (int i = 0; i < 8; ++i) x[i] = S[(u + 16*i) * STRIDE + c];
        fft128_inv(x, u, tw);
        #pragma unroll
        for (int i = 0; i < 8; ++i)
            lsum += fast_mag(x[i]);
    }
    float tot = block_sum(lsum, red, tid);
    if (tid == 0) g_s2p[blockIdx.x] = tot;
}

// ---------------- kernel 5: combine + MLP ----------------
__global__ void k_head(const float* __restrict__ fc1w, const float* __restrict__ fc1b,
                       const float* __restrict__ fc2w, const float* __restrict__ fc2b,
                       float* __restrict__ out) {
    int b = blockIdx.x;
    if (threadIdx.x != 0) return;
    float coeff[11];
    coeff[0] = g_s0[b];
    #pragma unroll
    for (int j = 0; j < 4; ++j) {
        float s = 0.0f;
        #pragma unroll
        for (int l = 0; l < 4; ++l) s += g_s1p[(b * 4 + j) * 4 + l];
        coeff[1 + j] = s * (1.0f / (4.0f * 16384.0f));
    }
    #pragma unroll
    for (int p = 0; p < 6; ++p) {
        float s = 0.0f;
        #pragma unroll
        for (int k = 0; k < 16; ++k) s += g_s2p[(b * 6 + p) * 16 + k];
        coeff[5 + p] = s * (1.0f / 16384.0f) * (1.0f / (16.0f * 16384.0f));
    }
    float h[4];
    #pragma unroll
    for (int k = 0; k < 4; ++k) {
        float a = fc1b[k];
        #pragma unroll
        for (int i = 0; i < 11; ++i) a += coeff[i] * fc1w[k * 11 + i];
        h[k] = fmaxf(a, 0.0f);
    }
    #pragma unroll
    for (int o = 0; o < 10; ++o) {
        float a = fc2b[o];
        #pragma unroll
        for (int k = 0; k < 4; ++k) a += h[k] * fc2w[o * 4 + k];
        out[b * 10 + o] = 1.0f / (1.0f + expf(-a));
    }
}

// ---------------- launch ----------------
extern "C" void kernel_launch(void* const* d_in, const int* in_sizes, int n_in,
                              void* d_out, int out_size) {
    (void)in_sizes; (void)n_in; (void)out_size;
    const float* img  = (const float*)d_in[0];
    const float* fc1w = (const float*)d_in[1];
    const float* fc1b = (const float*)d_in[2];
    const float* fc2w = (const float*)d_in[3];
    const float* fc2b = (const float*)d_in[4];
    float* out = (float*)d_out;

    const size_t SMEM_SZ = (size_t)(NN * STRIDE + 128) * sizeof(float2) + (NT / 32) * sizeof(float);
    cudaFuncSetAttribute(k_img, cudaFuncAttributeMaxDynamicSharedMemorySize, (int)SMEM_SZ);
    cudaFuncSetAttribute(k_o1,  cudaFuncAttributeMaxDynamicSharedMemorySize, (int)SMEM_SZ);
    cudaFuncSetAttribute(k_o2,  cudaFuncAttributeMaxDynamicSharedMemorySize, (int)SMEM_SZ);

    k_psi<<<(NJ * NL * PLANE + 255) / 256, 256>>>();
    k_img<<<BATCH, NT, SMEM_SZ>>>(img);
    k_o1 <<<BATCH * NJ * NL, NT, SMEM_SZ>>>();
    k_o2 <<<BATCH * NPAIR * NL * NL, NT, SMEM_SZ>>>();
    k_head<<<BATCH, 32>>>(fc1w, fc1b, fc2w, fc2b, out);
}